// round 9
// baseline (speedup 1.0000x reference)
#include <cuda_runtime.h>
#include <cuda_bf16.h>
#include <cstdint>

// x: [32,2048] int32 ids in [0,100000); W: [256,100000] f32 (EMBED-major);
// b: [256] f32; out: [65536,256] f32 = W[:, x[t]] + b.
//
// Single persistent kernel (all CTAs co-resident; software grid barriers):
//  A: rank[t] = atomicAdd(bins[id>>5],1)       (line-bucket histogram)
//  B: CTA0: offs = exscan(bins); bins = 0      (invariant restore)
//  C: sorted[offs[bin]+rank[t]] = {id,t}       (atomic-free scatter)
//  D: work-loop gather: 32 sorted tokens x 128 dims per job; coalesced
//     strided LDG -> STS.128 tile (stride 132, conflict-free) ->
//     LDS.128 + bias -> STG.128 evict-first contiguous rows.
static constexpr int VOCAB = 100000;
static constexpr int EMBED = 256;
static constexpr int NTOK  = 32 * 2048;            // 65536
static constexpr int NBINS = (VOCAB + 31) / 32;    // 3125
static constexpr int HDIM  = 128;                  // dims per job
static constexpr int TSTR  = 132;                  // tile stride (floats)
static constexpr int NJOBS = (NTOK / 32) * 2;      // 4096
static constexpr int MAXGRID = 1024;               // divides NJOBS evenly

__device__ int  g_bins[NBINS];     // zero at load; phase B re-zeroes
__device__ int  g_offs[NBINS];
__device__ int  g_rank[NTOK];
__device__ int2 g_sorted[NTOK];
__device__ unsigned          g_bar_count[3];
__device__ volatile unsigned g_bar_flag[3];
__device__ unsigned          g_done;

__device__ __forceinline__ int clamp_id(int v) {
    return min(max(v, 0), VOCAB - 1);
}

// Two-phase grid barrier; safe because grid <= co-resident capacity.
__device__ __forceinline__ void grid_barrier(int b, unsigned nctas) {
    __syncthreads();
    if (threadIdx.x == 0) {
        __threadfence();
        unsigned v = atomicAdd(&g_bar_count[b], 1);
        if (v == nctas - 1) {
            __threadfence();
            g_bar_flag[b] = 1;
        } else {
            while (g_bar_flag[b] == 0) __nanosleep(64);
        }
        __threadfence();
    }
    __syncthreads();
}

__global__ __launch_bounds__(256, 8) void fused_embedding_kernel(
    const int*   __restrict__ x,
    const float* __restrict__ W,
    const float* __restrict__ bias,
    float*       __restrict__ out)
{
    __shared__ __align__(16) float tile[32][TSTR];   // gather tile / scan buf
    __shared__ int s_id[32], s_tok[32];

    const int      tid   = threadIdx.x;
    const unsigned nctas = gridDim.x;
    const int      gtid  = blockIdx.x * 256 + tid;
    const int      nthr  = (int)nctas * 256;

    // ---- Phase A: histogram + per-token rank ----------------------------
    for (int t = gtid; t < NTOK; t += nthr) {
        int v = clamp_id(__ldg(&x[t]));
        g_rank[t] = atomicAdd(&g_bins[v >> 5], 1);
    }
    grid_barrier(0, nctas);

    // ---- Phase B: CTA0 exclusive scan (consume-and-zero bins) -----------
    if (blockIdx.x == 0) {
        int local[13];
        int s = 0;
        const int base = tid * 13;
#pragma unroll
        for (int k = 0; k < 13; ++k) {
            int idx = base + k;
            int c = (idx < NBINS) ? __ldcg(&g_bins[idx]) : 0;
            if (idx < NBINS) __stcg(&g_bins[idx], 0);
            local[k] = s; s += c;
        }
        int* partial = reinterpret_cast<int*>(&tile[0][0]);
        partial[tid] = s;
        __syncthreads();
        for (int off = 1; off < 256; off <<= 1) {    // Hillis-Steele
            int v = (tid >= off) ? partial[tid - off] : 0;
            __syncthreads();
            partial[tid] += v;
            __syncthreads();
        }
        int pbase = (tid > 0) ? partial[tid - 1] : 0;
#pragma unroll
        for (int k = 0; k < 13; ++k) {
            int idx = base + k;
            if (idx < NBINS) __stcg(&g_offs[idx], pbase + local[k]);
        }
    }
    grid_barrier(1, nctas);

    // ---- Phase C: atomic-free scatter ------------------------------------
    for (int t = gtid; t < NTOK; t += nthr) {
        int v = clamp_id(__ldg(&x[t]));
        int pos = __ldcg(&g_offs[v >> 5]) + __ldcg(&g_rank[t]);
        __stcg(&g_sorted[pos], make_int2(v, t));
    }
    grid_barrier(2, nctas);

    // ---- Phase D: gather work-loop --------------------------------------
    const int w = tid >> 5;          // warp -> dims [16w,16w+16) of the half
    const int l = tid & 31;          // lane -> sorted token
    for (int job = blockIdx.x; job < NJOBS; job += (int)nctas) {
        const int group = job >> 1;
        const int half  = job & 1;
        const int dim0  = half * HDIM;

        __syncthreads();             // tile/s_id reuse guard
        if (tid < 32) {
            int2 p = __ldcg(&g_sorted[group * 32 + tid]);
            s_id[tid]  = p.x;
            s_tok[tid] = p.y;
        }
        __syncthreads();

        const int vid = s_id[l];
        const float* wp = W + (size_t)(dim0 + w * 16) * VOCAB + (size_t)vid;
#pragma unroll
        for (int h = 0; h < 2; ++h) {                // 2x8 loads: fits 32 regs
            float rr[8];
#pragma unroll
            for (int j = 0; j < 8; ++j)
                rr[j] = __ldg(wp + (size_t)(h * 8 + j) * VOCAB);
#pragma unroll
            for (int j = 0; j < 2; ++j) {
                float4 v4 = make_float4(rr[4*j], rr[4*j+1], rr[4*j+2], rr[4*j+3]);
                *reinterpret_cast<float4*>(&tile[l][w * 16 + h * 8 + 4 * j]) = v4;
            }
        }
        __syncthreads();

        const float4 bv = __ldg(reinterpret_cast<const float4*>(bias) + half * 32 + l);
#pragma unroll
        for (int i = 0; i < 4; ++i) {
            const int t    = w * 4 + i;
            const int orig = s_tok[t];
            float4 v4 = *reinterpret_cast<const float4*>(&tile[t][4 * l]);
            v4.x += bv.x; v4.y += bv.y; v4.z += bv.z; v4.w += bv.w;
            __stcs(reinterpret_cast<float4*>(out + (size_t)orig * EMBED + dim0) + l, v4);
        }
    }

    // ---- Reset barrier state for next graph replay ----------------------
    __syncthreads();
    if (tid == 0) {
        unsigned v = atomicAdd(&g_done, 1);
        if (v == nctas - 1) {                        // last CTA: all spins done
            g_bar_count[0] = g_bar_count[1] = g_bar_count[2] = 0;
            g_bar_flag[0]  = g_bar_flag[1]  = g_bar_flag[2]  = 0;
            g_done = 0;
            __threadfence();
        }
    }
}

extern "C" void kernel_launch(void* const* d_in, const int* in_sizes, int n_in,
                              void* d_out, int out_size)
{
    const int*   x    = (const int*)d_in[0];
    const float* W    = (const float*)d_in[1];
    const float* bias = (const float*)d_in[2];
    float*       out  = (float*)d_out;

    // Size grid to guaranteed co-residency (spin barriers must not deadlock).
    int dev = 0;
    cudaGetDevice(&dev);
    int sms = 148;
    cudaDeviceGetAttribute(&sms, cudaDevAttrMultiProcessorCount, dev);
    int maxb = 0;
    cudaOccupancyMaxActiveBlocksPerMultiprocessor(&maxb, fused_embedding_kernel, 256, 0);
    if (maxb < 1) maxb = 1;
    int grid = sms * maxb;
    if (grid > MAXGRID) grid = MAXGRID;

    fused_embedding_kernel<<<grid, 256>>>(x, W, bias, out);
}